// round 15
// baseline (speedup 1.0000x reference)
#include <cuda_runtime.h>
#include <math.h>
#include <stdint.h>

#define D     1024
#define NV    128
#define BATCH 32768

// Scratch (static device globals)
__device__ float g_Utf [D * NV];      // tf32 bits of normalized U  (stage1 B: [d][k])
__device__ float g_csq [128 * NV];    // column sum-of-squares partials
__device__ float g_Gp  [8 * NV * NV]; // Gram partials (K-split by 8)
__device__ float g_M   [NV * NV];     // M = 2T, fp32, [k][j]
__device__ float g_R   [NV * D];      // R = M @ U^T, tf32 bits, [k][d]

__device__ __forceinline__ unsigned f2tf(float f) {
    unsigned r;
    asm("cvt.rna.tf32.f32 %0, %1;" : "=r"(r) : "f"(f));
    return r;
}

// ---------------------------------------------------------------------------
// Setup A: column sum-of-squares partials. grid 128, block 128.
// ---------------------------------------------------------------------------
__global__ void k_colsq(const float* __restrict__ v) {
    const int col = threadIdx.x;
    const int r0  = blockIdx.x * 8;
    float s = 0.f;
#pragma unroll
    for (int r = 0; r < 8; r++) {
        float t = v[(r0 + r) * NV + col];
        s += t * t;
    }
    g_csq[blockIdx.x * NV + col] = s;
}

// ---------------------------------------------------------------------------
// Setup B: normalize + tf32-convert. grid (8,4), block (32,8).
// ---------------------------------------------------------------------------
__global__ void k_prep(const float* __restrict__ v) {
    const int tx = threadIdx.x, ty = threadIdx.y;
    const int d0 = blockIdx.x * 128;
    const int k0 = blockIdx.y * 32;

    __shared__ float part[8][33];
    __shared__ float sinv[32];

    float ps = 0.f;
    for (int s = ty; s < 128; s += 8) ps += g_csq[s * NV + k0 + tx];
    part[ty][tx] = ps;
    __syncthreads();
    if (ty == 0) {
        float tot = 0.f;
#pragma unroll
        for (int q = 0; q < 8; q++) tot += part[q][tx];
        sinv[tx] = rsqrtf(tot);
    }
    __syncthreads();
    const float inv = sinv[tx];

#pragma unroll
    for (int rr = 0; rr < 16; rr++) {
        int d = d0 + ty * 16 + rr;
        float u = v[d * NV + k0 + tx] * inv;
        g_Utf[d * NV + k0 + tx] = __uint_as_float(f2tf(u));
    }
}

// ---------------------------------------------------------------------------
// Setup C: Gram partials G = Utf^T Utf. grid (16, 8), 128 threads.
// ---------------------------------------------------------------------------
__global__ void k_gram() {
    const int i  = threadIdx.x;
    const int jb = blockIdx.x * 8;
    const int s  = blockIdx.y;
    float acc[8] = {0, 0, 0, 0, 0, 0, 0, 0};
    const int d0 = s * 128;
#pragma unroll 2
    for (int d = d0; d < d0 + 128; d++) {
        float ui = g_Utf[d * NV + i];
#pragma unroll
        for (int q = 0; q < 8; q++) acc[q] += ui * g_Utf[d * NV + jb + q];
    }
#pragma unroll
    for (int q = 0; q < 8; q++) g_Gp[s * NV * NV + i * NV + jb + q] = acc[q];
}

// ---------------------------------------------------------------------------
// Setup D: M = 2 * W^{-1}, W = I + 2*strictupper(G). Single CTA, 256 threads.
// ---------------------------------------------------------------------------
__global__ void k_buildM() {
    extern __shared__ float sm[];
    float* sW = sm;                    // 128*129
    float* sX = sm + 128 * 129;        // 128*129
    float* sP = sm + 2 * 128 * 129;    // 64*65 scratch
    const int tid = threadIdx.x;       // 256 threads

    {
        const float4* gp4 = (const float4*)g_Gp;
#pragma unroll 4
        for (int q4 = tid; q4 < (NV * NV) / 4; q4 += 256) {
            float4 a = gp4[q4];
#pragma unroll
            for (int s = 1; s < 8; s++) {
                float4 t = gp4[s * (NV * NV / 4) + q4];
                a.x += t.x; a.y += t.y; a.z += t.z; a.w += t.w;
            }
            int base = q4 * 4;
            int r = base >> 7, c = base & 127;
            float* wdst = &sW[r * 129 + c];
            wdst[0] = 2.f * a.x; wdst[1] = 2.f * a.y;
            wdst[2] = 2.f * a.z; wdst[3] = 2.f * a.w;
            float* xdst = &sX[r * 129 + c];
            xdst[0] = (r == c)     ? 1.f : 0.f;
            xdst[1] = (r == c + 1) ? 1.f : 0.f;
            xdst[2] = (r == c + 2) ? 1.f : 0.f;
            xdst[3] = (r == c + 3) ? 1.f : 0.f;
        }
    }
    __syncthreads();

    if (tid < 128) {
        const int w = tid >> 5, t = tid & 31, b = w * 32;
        const float* Wb = &sW[b * 129 + b];
        float xr[32];
#pragma unroll
        for (int j = 0; j < 32; j++) xr[j] = (j == t) ? 1.f : 0.f;
#pragma unroll
        for (int m = 1; m < 32; m++) {
            float acc = 0.f;
#pragma unroll
            for (int j = 0; j < m; j++) acc += xr[j] * Wb[j * 129 + m];
            xr[m] = (t < m) ? -acc : xr[m];
        }
        float* Xb = &sX[(b + t) * 129 + b];
#pragma unroll
        for (int j = 0; j < 32; j++) Xb[j] = xr[j];
    }
    __syncthreads();

    {   // combine 32 -> 64 (two pairs)
        const int p  = tid >> 7, tl = tid & 127;
        const int b1 = p * 64, b2 = p * 64 + 32;
        float* P = &sP[p * 32 * 33];
#pragma unroll
        for (int i = 0; i < 8; i++) {
            int idx = tl + i * 128, r = idx >> 5, c = idx & 31;
            float acc = 0.f;
#pragma unroll 8
            for (int k = 0; k < 32; k++)
                acc += sW[(b1 + r) * 129 + b2 + k] * sX[(b2 + k) * 129 + b2 + c];
            P[r * 33 + c] = acc;
        }
        __syncthreads();
#pragma unroll
        for (int i = 0; i < 8; i++) {
            int idx = tl + i * 128, r = idx >> 5, c = idx & 31;
            float acc = 0.f;
#pragma unroll 8
            for (int k = 0; k < 32; k++)
                acc += sX[(b1 + r) * 129 + b1 + k] * P[k * 33 + c];
            sX[(b1 + r) * 129 + b2 + c] = -acc;
        }
    }
    __syncthreads();

    {   // combine 64 -> 128
        const int ty = tid >> 4, tx = tid & 15;
        const int r0 = ty * 4, c0 = tx * 4;
        float acc[4][4];
#pragma unroll
        for (int r = 0; r < 4; r++)
#pragma unroll
            for (int c = 0; c < 4; c++) acc[r][c] = 0.f;
#pragma unroll 4
        for (int k = 0; k < 64; k++) {
            float a[4], bv[4];
#pragma unroll
            for (int r = 0; r < 4; r++) a[r] = sW[(r0 + r) * 129 + 64 + k];
#pragma unroll
            for (int c = 0; c < 4; c++) bv[c] = sX[(64 + k) * 129 + 64 + c0 + c];
#pragma unroll
            for (int r = 0; r < 4; r++)
#pragma unroll
                for (int c = 0; c < 4; c++) acc[r][c] += a[r] * bv[c];
        }
#pragma unroll
        for (int r = 0; r < 4; r++)
#pragma unroll
            for (int c = 0; c < 4; c++) sP[(r0 + r) * 65 + c0 + c] = acc[r][c];
        __syncthreads();
#pragma unroll
        for (int r = 0; r < 4; r++)
#pragma unroll
            for (int c = 0; c < 4; c++) acc[r][c] = 0.f;
#pragma unroll 4
        for (int k = 0; k < 64; k++) {
            float a[4], bv[4];
#pragma unroll
            for (int r = 0; r < 4; r++) a[r] = sX[(r0 + r) * 129 + k];
#pragma unroll
            for (int c = 0; c < 4; c++) bv[c] = sP[k * 65 + c0 + c];
#pragma unroll
            for (int r = 0; r < 4; r++)
#pragma unroll
                for (int c = 0; c < 4; c++) acc[r][c] += a[r] * bv[c];
        }
#pragma unroll
        for (int r = 0; r < 4; r++)
#pragma unroll
            for (int c = 0; c < 4; c++)
                sX[(r0 + r) * 129 + 64 + c0 + c] = -acc[r][c];
    }
    __syncthreads();

    for (int idx = tid; idx < NV * NV; idx += 256) {
        int r = idx >> 7, c = idx & 127;
        g_M[idx] = 2.f * sX[r * 129 + c];
    }
}

// ---------------------------------------------------------------------------
// Setup E: R[k][d] = sum_j M[k][j] * U[d][j], tf32 bits. grid 64, block 256.
// ---------------------------------------------------------------------------
__global__ void k_mkR() {
    extern __shared__ float smr[];
    float* sM = smr;                 // 128*129
    float* sU = smr + 128 * 129;     // 16*132
    const int tid = threadIdx.x;
    const int d0  = blockIdx.x * 16;

    for (int i = tid; i < NV * NV; i += 256)
        sM[(i >> 7) * 129 + (i & 127)] = g_M[i];
    for (int e = tid; e < 16 * 128; e += 256) {
        int q = e >> 7, j = e & 127;
        sU[q * 132 + j] = g_Utf[(d0 + q) * NV + j];
    }
    __syncthreads();

    const int k    = tid & 127;
    const int half = tid >> 7;
    float acc[8] = {0, 0, 0, 0, 0, 0, 0, 0};
    const float* mrow = &sM[k * 129];
    const float* ub   = &sU[half * 8 * 132];
#pragma unroll 4
    for (int j = 0; j < NV; j++) {
        float m = mrow[j];
#pragma unroll
        for (int q = 0; q < 8; q++) acc[q] += m * ub[q * 132 + j];
    }
#pragma unroll
    for (int q = 0; q < 8; q++)
        g_R[k * D + d0 + half * 8 + q] = __uint_as_float(f2tf(acc[q]));
}

// ---------------------------------------------------------------------------
// Fused tensor-core kernel, 64-row CTAs (grid 512), 32x64 warp tiles,
// ldmatrix A-fragments, STATIC double-buffered cp.async B tiles (us0/us1,
// compile-time offsets, wait_group 1). x stays on register-prefetch path.
// ---------------------------------------------------------------------------
#define XS 36
#define US 136
#define YS 132

#define OFF_XS  0        // 64*36  = 2304
#define OFF_US0 2304     // 32*136 = 4352
#define OFF_US1 6656     // 32*136 = 4352
#define OFF_YS  11008    // 64*132 = 8448
#define SM_FLOATS 19456  // 77,824 bytes

__device__ __forceinline__ uint32_t smem_u32(const void* p) {
    uint32_t a;
    asm("{ .reg .u64 t; cvta.to.shared.u64 t, %1; cvt.u32.u64 %0, t; }"
        : "=r"(a) : "l"(p));
    return a;
}
__device__ __forceinline__ void cpa16(uint32_t dst, const void* src) {
    asm volatile("cp.async.cg.shared.global [%0], [%1], 16;" :: "r"(dst), "l"(src));
}
#define CPA_COMMIT() asm volatile("cp.async.commit_group;" ::: "memory")
#define CPA_WAIT1()  asm volatile("cp.async.wait_group 1;" ::: "memory")
#define CPA_WAIT0()  asm volatile("cp.async.wait_group 0;" ::: "memory")

__device__ __forceinline__ void mma8(float c[4], const unsigned a[4], const unsigned b[2]) {
    asm volatile(
        "mma.sync.aligned.m16n8k8.row.col.f32.tf32.tf32.f32 "
        "{%0,%1,%2,%3}, {%4,%5,%6,%7}, {%8,%9}, {%0,%1,%2,%3};"
        : "+f"(c[0]), "+f"(c[1]), "+f"(c[2]), "+f"(c[3])
        : "r"(a[0]), "r"(a[1]), "r"(a[2]), "r"(a[3]), "r"(b[0]), "r"(b[1]));
}

__device__ __forceinline__ void ldsm4(unsigned a[4], uint32_t addr) {
    asm volatile("ldmatrix.sync.aligned.m8n8.x4.shared.b16 {%0,%1,%2,%3}, [%4];"
        : "=r"(a[0]), "=r"(a[1]), "=r"(a[2]), "=r"(a[3]) : "r"(addr));
}

__global__ __launch_bounds__(128, 2) void k_fused(const float* __restrict__ x,
                                                  const float* __restrict__ bias,
                                                  float* __restrict__ out) {
    extern __shared__ float smf[];
    float* xs = smf + OFF_XS;
    float* ys = smf + OFF_YS;
    const uint32_t sb    = smem_u32(smf);
    const uint32_t xs_b  = sb + OFF_XS * 4;
    const uint32_t us0_b = sb + OFF_US0 * 4;
    const uint32_t us1_b = sb + OFF_US1 * 4;
    const uint32_t ys_b  = sb + OFF_YS * 4;
    const unsigned* us0u = (const unsigned*)(smf + OFF_US0);
    const unsigned* us1u = (const unsigned*)(smf + OFF_US1);

    const int tid  = threadIdx.x;
    const int lane = tid & 31, wid = tid >> 5;       // 4 warps
    const int wm = wid >> 1, wn = wid & 1;           // 2x2 warp grid
    const int grp = lane >> 2, tg = lane & 3;
    const int rowBase = blockIdx.x * 64;
    const int wrow = wm * 32;
    const int wcol = wn * 64;

    const int lmRow = lane & 15;
    const int lmCol = (lane >> 4) << 2;

    const int xr0 = tid >> 3, xc4 = tid & 7;     // x fill map
    const int ukr = tid >> 5, uc4 = tid & 31;    // B fill map (8 its x 4 rows)
    const uint32_t uOff = ((ukr)*US + uc4 * 4) * 4;   // base byte offset within buffer

    float acc[2][8][4];

#define FILL_B(bufb, srcptr)                                                   \
    _Pragma("unroll")                                                          \
    for (int it = 0; it < 8; it++)                                             \
        cpa16((bufb) + uOff + it * (4 * US * 4),                               \
              (srcptr) + (size_t)(it * 4) * 0 + 0);

    // (macro above unused — explicit loops below for clarity)

    // ======== Stage 1: Y = x @ U ========
#pragma unroll
    for (int mf = 0; mf < 2; mf++)
#pragma unroll
        for (int nf = 0; nf < 8; nf++)
#pragma unroll
            for (int q = 0; q < 4; q++) acc[mf][nf][q] = 0.f;

    float4 p[4];
#pragma unroll
    for (int it = 0; it < 4; it++)
        p[it] = *(const float4*)&x[(size_t)(rowBase + xr0 + it * 16) * D + xc4 * 4];

    // prologue: B(0) -> us0
#pragma unroll
    for (int it = 0; it < 8; it++)
        cpa16(us0_b + ((ukr + it * 4) * US + uc4 * 4) * 4,
              &g_Utf[(ukr + it * 4) * NV + uc4 * 4]);
    CPA_COMMIT();

#define S1_COMPUTE(USU)                                                        \
    _Pragma("unroll")                                                          \
    for (int k8 = 0; k8 < 4; k8++) {                                           \
        const int kb = k8 * 8;                                                 \
        unsigned A[2][4], B[8][2];                                             \
        _Pragma("unroll")                                                      \
        for (int mf = 0; mf < 2; mf++)                                         \
            ldsm4(A[mf], xs_b + ((wrow + mf * 16 + lmRow) * XS + kb + lmCol) * 4); \
        _Pragma("unroll")                                                      \
        for (int nf = 0; nf < 8; nf++) {                                       \
            int c = wcol + nf * 8 + grp;                                       \
            B[nf][0] = (USU)[(kb + tg) * US + c];                              \
            B[nf][1] = (USU)[(kb + tg + 4) * US + c];                          \
        }                                                                      \
        _Pragma("unroll")                                                      \
        for (int mf = 0; mf < 2; mf++)                                         \
            _Pragma("unroll")                                                  \
            for (int nf = 0; nf < 8; nf++)                                     \
                mma8(acc[mf][nf], A[mf], B[nf]);                               \
    }

    for (int kt = 0; kt < 32; kt += 2) {
        // ---- even tile: compute us0, prefetch B(kt+1) -> us1 ----
#pragma unroll
        for (int it = 0; it < 4; it++)
            *(float4*)&xs[(xr0 + it * 16) * XS + xc4 * 4] = p[it];
#pragma unroll
        for (int it = 0; it < 8; it++)
            cpa16(us1_b + ((ukr + it * 4) * US + uc4 * 4) * 4,
                  &g_Utf[((kt + 1) * 32 + ukr + it * 4) * NV + uc4 * 4]);
        CPA_COMMIT();
        CPA_WAIT1();
        __syncthreads();
#pragma unroll
        for (int it = 0; it < 4; it++)
            p[it] = *(const float4*)&x[(size_t)(rowBase + xr0 + it * 16) * D +
                                       (kt + 1) * 32 + xc4 * 4];
        S1_COMPUTE(us0u);
        __syncthreads();

        // ---- odd tile: compute us1, prefetch B(kt+2) -> us0 ----
#pragma unroll
        for (int it = 0; it < 4; it++)
            *(float4*)&xs[(xr0 + it * 16) * XS + xc4 * 4] = p[it];
        if (kt + 2 < 32) {
#pragma unroll
            for (int it = 0; it < 8; it++)
                cpa16(us0_b + ((ukr + it * 4) * US + uc4 * 4) * 4,
                      &g_Utf[((kt + 2) * 32 + ukr + it * 4) * NV + uc4 * 4]);
            CPA_COMMIT();
            CPA_WAIT1();
        } else {
            CPA_WAIT0();
        }
        __syncthreads();
        if (kt + 2 < 32) {
#pragma unroll
            for (int it = 0; it < 4; it++)
                p[it] = *(const float4*)&x[(size_t)(rowBase + xr0 + it * 16) * D +
                                           (kt + 2) * 32 + xc4 * 4];
        }
        S1_COMPUTE(us1u);
        __syncthreads();
    }

    // Y -> ys (tf32 bits)
#pragma unroll
    for (int mf = 0; mf < 2; mf++)
#pragma unroll
        for (int nf = 0; nf < 8; nf++) {
            int r = wrow + mf * 16 + grp, c = wcol + nf * 8 + tg * 2;
            ys[r * YS + c]           = __uint_as_float(f2tf(acc[mf][nf][0]));
            ys[r * YS + c + 1]       = __uint_as_float(f2tf(acc[mf][nf][1]));
            ys[(r + 8) * YS + c]     = __uint_as_float(f2tf(acc[mf][nf][2]));
            ys[(r + 8) * YS + c + 1] = __uint_as_float(f2tf(acc[mf][nf][3]));
        }

    // ======== Stage 2: out = x - Y @ R + b ========
    // flattened tiles t = 0..31: dB = (t>>2)*128, mt = t&3
#pragma unroll
    for (int mf = 0; mf < 2; mf++)
#pragma unroll
        for (int nf = 0; nf < 8; nf++)
#pragma unroll
            for (int q = 0; q < 4; q++) acc[mf][nf][q] = 0.f;

#define S2_COMPUTE(USU, KG0)                                                   \
    _Pragma("unroll")                                                          \
    for (int k8 = 0; k8 < 4; k8++) {                                           \
        const int kb = k8 * 8;                                                 \
        const int kg = (KG0) + kb;                                             \
        unsigned A[2][4], B[8][2];                                             \
        _Pragma("unroll")                                                      \
        for (int mf = 0; mf < 2; mf++)                                         \
            ldsm4(A[mf], ys_b + ((wrow + mf * 16 + lmRow) * YS + kg + lmCol) * 4); \
        _Pragma("unroll")                                                      \
        for (int nf = 0; nf < 8; nf++) {                                       \
            int c = wcol + nf * 8 + grp;                                       \
            B[nf][0] = (USU)[(kb + tg) * US + c];                              \
            B[nf][1] = (USU)[(kb + tg + 4) * US + c];                          \
        }                                                                      \
        _Pragma("unroll")                                                      \
        for (int mf = 0; mf < 2; mf++)                                         \
            _Pragma("unroll")                                                  \
            for (int nf = 0; nf < 8; nf++)                                     \
                mma8(acc[mf][nf], A[mf], B[nf]);                               \
    }

#define S2_EPILOGUE(DB)                                                        \
    _Pragma("unroll")                                                          \
    for (int mf = 0; mf < 2; mf++)                                             \
        _Pragma("unroll")                                                      \
        for (int nf = 0; nf < 8; nf++) {                                       \
            int r = rowBase + wrow + mf * 16 + grp;                            \
            int c = (DB) + wcol + nf * 8 + tg * 2;                             \
            float2 bv = *(const float2*)&bias[c];                              \
            float2 x0 = *(const float2*)&x[(size_t)r * D + c];                 \
            float2 x1 = *(const float2*)&x[(size_t)(r + 8) * D + c];           \
            float2 o0, o1;                                                     \
            o0.x = x0.x + bv.x - acc[mf][nf][0];                               \
            o0.y = x0.y + bv.y - acc[mf][nf][1];                               \
            o1.x = x1.x + bv.x - acc[mf][nf][2];                               \
            o1.y = x1.y + bv.y - acc[mf][nf][3];                               \
            *(float2*)&out[(size_t)r * D + c]       = o0;                      \
            *(float2*)&out[(size_t)(r + 8) * D + c] = o1;                      \
            acc[mf][nf][0] = 0.f; acc[mf][nf][1] = 0.f;                        \
            acc[mf][nf][2] = 0.f; acc[mf][nf][3] = 0.f;                        \
        }

    // prologue: tile 0 -> us0
#pragma unroll
    for (int it = 0; it < 8; it++)
        cpa16(us0_b + ((ukr + it * 4) * US + uc4 * 4) * 4,
              &g_R[(size_t)(ukr + it * 4) * D + uc4 * 4]);
    CPA_COMMIT();

    for (int t = 0; t < 32; t += 2) {
        // ---- even tile t: compute us0, prefetch t+1 -> us1 ----
        {
            const int mt1 = (t + 1) & 3, dB1 = ((t + 1) >> 2) * 128;
#pragma unroll
            for (int it = 0; it < 8; it++)
                cpa16(us1_b + ((ukr + it * 4) * US + uc4 * 4) * 4,
                      &g_R[(size_t)(mt1 * 32 + ukr + it * 4) * D + dB1 + uc4 * 4]);
            CPA_COMMIT();
            CPA_WAIT1();
        }
        __syncthreads();   // also covers Y->ys visibility at t=0
        S2_COMPUTE(us0u, (t & 3) * 32);
        // t even -> (t&3) != 3, no epilogue
        __syncthreads();

        // ---- odd tile t+1: compute us1, prefetch t+2 -> us0 ----
        if (t + 2 < 32) {
            const int mt2 = (t + 2) & 3, dB2 = ((t + 2) >> 2) * 128;
#pragma unroll
            for (int it = 0; it < 8; it++)
                cpa16(us0_b + ((ukr + it * 4) * US + uc4 * 4) * 4,
                      &g_R[(size_t)(mt2 * 32 + ukr + it * 4) * D + dB2 + uc4 * 4]);
            CPA_COMMIT();
            CPA_WAIT1();
        } else {
            CPA_WAIT0();
        }
        __syncthreads();
        S2_COMPUTE(us1u, ((t + 1) & 3) * 32);
        if (((t + 1) & 3) == 3) {
            S2_EPILOGUE(((t + 1) >> 2) * 128);
        }
        __syncthreads();
    }
}

// ---------------------------------------------------------------------------
extern "C" void kernel_launch(void* const* d_in, const int* in_sizes, int n_in,
                              void* d_out, int out_size) {
    const float* x = nullptr;
    const float* v = nullptr;
    const float* b = nullptr;
    for (int i = 0; i < n_in; i++) {
        if      (in_sizes[i] == BATCH * D) x = (const float*)d_in[i];
        else if (in_sizes[i] == D * NV)    v = (const float*)d_in[i];
        else if (in_sizes[i] == D)         b = (const float*)d_in[i];
    }
    float* out = (float*)d_out;

    const size_t smemM     = (2 * 128 * 129 + 64 * 65) * sizeof(float); // ~145 KB
    const size_t smemR     = (128 * 129 + 16 * 132) * sizeof(float);    // ~74 KB
    const size_t smemFused = SM_FLOATS * sizeof(float);                 // 77.8 KB
    cudaFuncSetAttribute(k_buildM, cudaFuncAttributeMaxDynamicSharedMemorySize, (int)smemM);
    cudaFuncSetAttribute(k_mkR,    cudaFuncAttributeMaxDynamicSharedMemorySize, (int)smemR);
    cudaFuncSetAttribute(k_fused,  cudaFuncAttributeMaxDynamicSharedMemorySize, (int)smemFused);

    k_colsq <<<128, 128>>>(v);
    k_prep  <<<dim3(8, 4), dim3(32, 8)>>>(v);
    k_gram  <<<dim3(16, 8), 128>>>();
    k_buildM<<<1, 256, smemM>>>();
    k_mkR   <<<64, 256, smemR>>>();
    k_fused <<<BATCH / 64, 128, smemFused>>>(x, b, out);
}

// round 16
// speedup vs baseline: 1.1158x; 1.1158x over previous
#include <cuda_runtime.h>
#include <cuda_fp16.h>
#include <math.h>
#include <stdint.h>

#define D     1024
#define NV    128
#define BATCH 32768

// Scratch (static device globals)
__device__ float  g_Utf[D * NV];       // fp32 values of half-rounded U, [d][k] (gram/mkR)
__device__ __half g_Uh [NV * D];       // half U^T: g_Uh[n][d]  (stage1 B, n-major)
__device__ float  g_csq[128 * NV];     // column sum-of-squares partials
__device__ float  g_Gp [8 * NV * NV];  // Gram partials (K-split by 8)
__device__ float  g_M  [NV * NV];      // M = 2T, fp32, [k][j]
__device__ __half g_Rh [D * NV];       // half R^T: g_Rh[d][k]  (stage2 B, n-major)

// ---------------------------------------------------------------------------
// Setup A: column sum-of-squares partials. grid 128, block 128.
// ---------------------------------------------------------------------------
__global__ void k_colsq(const float* __restrict__ v) {
    const int col = threadIdx.x;
    const int r0  = blockIdx.x * 8;
    float s = 0.f;
#pragma unroll
    for (int r = 0; r < 8; r++) {
        float t = v[(r0 + r) * NV + col];
        s += t * t;
    }
    g_csq[blockIdx.x * NV + col] = s;
}

// ---------------------------------------------------------------------------
// Setup B: normalize + half-convert. grid (8,4), block (32,8).
// Writes g_Utf (fp32 of half-rounded u, [d][k]) and g_Uh ([k][d] half, via
// smem transpose for coalesced writes).
// ---------------------------------------------------------------------------
__global__ void k_prep(const float* __restrict__ v) {
    const int tx = threadIdx.x, ty = threadIdx.y;
    const int tid = ty * 32 + tx;
    const int d0 = blockIdx.x * 128;
    const int k0 = blockIdx.y * 32;

    __shared__ float part[8][33];
    __shared__ float sinv[32];
    __shared__ __half tile_h[32 * 136];   // [n-local][d-local], pad 136

    float ps = 0.f;
    for (int s = ty; s < 128; s += 8) ps += g_csq[s * NV + k0 + tx];
    part[ty][tx] = ps;
    __syncthreads();
    if (ty == 0) {
        float tot = 0.f;
#pragma unroll
        for (int q = 0; q < 8; q++) tot += part[q][tx];
        sinv[tx] = rsqrtf(tot);
    }
    __syncthreads();
    const float inv = sinv[tx];

#pragma unroll
    for (int rr = 0; rr < 16; rr++) {
        int dd = ty * 16 + rr;
        int d  = d0 + dd;
        float u = v[d * NV + k0 + tx] * inv;
        __half h = __float2half_rn(u);
        g_Utf[d * NV + k0 + tx] = __half2float(h);
        tile_h[tx * 136 + dd] = h;
    }
    __syncthreads();

    // coalesced write of 32 rows x 128 halves (32B chunks)
    {
        int tloc = tid >> 3, chunk = tid & 7;   // 32 rows x 8 chunks of 16 halves
        const uint4* src = (const uint4*)&tile_h[tloc * 136 + chunk * 16];
        uint4* dst = (uint4*)&g_Uh[(size_t)(k0 + tloc) * D + d0 + chunk * 16];
        dst[0] = src[0];
        dst[1] = src[1];
    }
}

// ---------------------------------------------------------------------------
// Setup C: Gram partials G = Utf^T Utf. grid (16, 8), 128 threads.
// ---------------------------------------------------------------------------
__global__ void k_gram() {
    const int i  = threadIdx.x;
    const int jb = blockIdx.x * 8;
    const int s  = blockIdx.y;
    float acc[8] = {0, 0, 0, 0, 0, 0, 0, 0};
    const int d0 = s * 128;
#pragma unroll 2
    for (int d = d0; d < d0 + 128; d++) {
        float ui = g_Utf[d * NV + i];
#pragma unroll
        for (int q = 0; q < 8; q++) acc[q] += ui * g_Utf[d * NV + jb + q];
    }
#pragma unroll
    for (int q = 0; q < 8; q++) g_Gp[s * NV * NV + i * NV + jb + q] = acc[q];
}

// ---------------------------------------------------------------------------
// Setup D: M = 2 * W^{-1}, W = I + 2*strictupper(G). Single CTA, 256 threads.
// ---------------------------------------------------------------------------
__global__ void k_buildM() {
    extern __shared__ float sm[];
    float* sW = sm;                    // 128*129
    float* sX = sm + 128 * 129;        // 128*129
    float* sP = sm + 2 * 128 * 129;    // 64*65 scratch
    const int tid = threadIdx.x;       // 256 threads

    {
        const float4* gp4 = (const float4*)g_Gp;
#pragma unroll 4
        for (int q4 = tid; q4 < (NV * NV) / 4; q4 += 256) {
            float4 a = gp4[q4];
#pragma unroll
            for (int s = 1; s < 8; s++) {
                float4 t = gp4[s * (NV * NV / 4) + q4];
                a.x += t.x; a.y += t.y; a.z += t.z; a.w += t.w;
            }
            int base = q4 * 4;
            int r = base >> 7, c = base & 127;
            float* wdst = &sW[r * 129 + c];
            wdst[0] = 2.f * a.x; wdst[1] = 2.f * a.y;
            wdst[2] = 2.f * a.z; wdst[3] = 2.f * a.w;
            float* xdst = &sX[r * 129 + c];
            xdst[0] = (r == c)     ? 1.f : 0.f;
            xdst[1] = (r == c + 1) ? 1.f : 0.f;
            xdst[2] = (r == c + 2) ? 1.f : 0.f;
            xdst[3] = (r == c + 3) ? 1.f : 0.f;
        }
    }
    __syncthreads();

    if (tid < 128) {
        const int w = tid >> 5, t = tid & 31, b = w * 32;
        const float* Wb = &sW[b * 129 + b];
        float xr[32];
#pragma unroll
        for (int j = 0; j < 32; j++) xr[j] = (j == t) ? 1.f : 0.f;
#pragma unroll
        for (int m = 1; m < 32; m++) {
            float acc = 0.f;
#pragma unroll
            for (int j = 0; j < m; j++) acc += xr[j] * Wb[j * 129 + m];
            xr[m] = (t < m) ? -acc : xr[m];
        }
        float* Xb = &sX[(b + t) * 129 + b];
#pragma unroll
        for (int j = 0; j < 32; j++) Xb[j] = xr[j];
    }
    __syncthreads();

    {   // combine 32 -> 64 (two pairs)
        const int p  = tid >> 7, tl = tid & 127;
        const int b1 = p * 64, b2 = p * 64 + 32;
        float* P = &sP[p * 32 * 33];
#pragma unroll
        for (int i = 0; i < 8; i++) {
            int idx = tl + i * 128, r = idx >> 5, c = idx & 31;
            float acc = 0.f;
#pragma unroll 8
            for (int k = 0; k < 32; k++)
                acc += sW[(b1 + r) * 129 + b2 + k] * sX[(b2 + k) * 129 + b2 + c];
            P[r * 33 + c] = acc;
        }
        __syncthreads();
#pragma unroll
        for (int i = 0; i < 8; i++) {
            int idx = tl + i * 128, r = idx >> 5, c = idx & 31;
            float acc = 0.f;
#pragma unroll 8
            for (int k = 0; k < 32; k++)
                acc += sX[(b1 + r) * 129 + b1 + k] * P[k * 33 + c];
            sX[(b1 + r) * 129 + b2 + c] = -acc;
        }
    }
    __syncthreads();

    {   // combine 64 -> 128
        const int ty = tid >> 4, tx = tid & 15;
        const int r0 = ty * 4, c0 = tx * 4;
        float acc[4][4];
#pragma unroll
        for (int r = 0; r < 4; r++)
#pragma unroll
            for (int c = 0; c < 4; c++) acc[r][c] = 0.f;
#pragma unroll 4
        for (int k = 0; k < 64; k++) {
            float a[4], bv[4];
#pragma unroll
            for (int r = 0; r < 4; r++) a[r] = sW[(r0 + r) * 129 + 64 + k];
#pragma unroll
            for (int c = 0; c < 4; c++) bv[c] = sX[(64 + k) * 129 + 64 + c0 + c];
#pragma unroll
            for (int r = 0; r < 4; r++)
#pragma unroll
                for (int c = 0; c < 4; c++) acc[r][c] += a[r] * bv[c];
        }
#pragma unroll
        for (int r = 0; r < 4; r++)
#pragma unroll
            for (int c = 0; c < 4; c++) sP[(r0 + r) * 65 + c0 + c] = acc[r][c];
        __syncthreads();
#pragma unroll
        for (int r = 0; r < 4; r++)
#pragma unroll
            for (int c = 0; c < 4; c++) acc[r][c] = 0.f;
#pragma unroll 4
        for (int k = 0; k < 64; k++) {
            float a[4], bv[4];
#pragma unroll
            for (int r = 0; r < 4; r++) a[r] = sX[(r0 + r) * 129 + k];
#pragma unroll
            for (int c = 0; c < 4; c++) bv[c] = sP[k * 65 + c0 + c];
#pragma unroll
            for (int r = 0; r < 4; r++)
#pragma unroll
                for (int c = 0; c < 4; c++) acc[r][c] += a[r] * bv[c];
        }
#pragma unroll
        for (int r = 0; r < 4; r++)
#pragma unroll
            for (int c = 0; c < 4; c++)
                sX[(r0 + r) * 129 + 64 + c0 + c] = -acc[r][c];
    }
    __syncthreads();

    for (int idx = tid; idx < NV * NV; idx += 256) {
        int r = idx >> 7, c = idx & 127;
        g_M[idx] = 2.f * sX[r * 129 + c];
    }
}

// ---------------------------------------------------------------------------
// Setup E: R[k][d] = sum_j M[k][j] * U[d][j]; write g_Rh[d][k] (half).
// grid 64, block 256: block = 16 d-cols; k = tid&127, half-sel = tid>>7.
// ---------------------------------------------------------------------------
__global__ void k_mkR() {
    extern __shared__ float smr[];
    float* sM = smr;                 // 128*129
    float* sU = smr + 128 * 129;     // 16*132
    const int tid = threadIdx.x;
    const int d0  = blockIdx.x * 16;

    for (int i = tid; i < NV * NV; i += 256)
        sM[(i >> 7) * 129 + (i & 127)] = g_M[i];
    for (int e = tid; e < 16 * 128; e += 256) {
        int q = e >> 7, j = e & 127;
        sU[q * 132 + j] = g_Utf[(d0 + q) * NV + j];
    }
    __syncthreads();

    const int k  = tid & 127;
    const int hf = tid >> 7;
    float acc[8] = {0, 0, 0, 0, 0, 0, 0, 0};
    const float* mrow = &sM[k * 129];
    const float* ub   = &sU[hf * 8 * 132];
#pragma unroll 4
    for (int j = 0; j < NV; j++) {
        float m = mrow[j];
#pragma unroll
        for (int q = 0; q < 8; q++) acc[q] += m * ub[q * 132 + j];
    }
#pragma unroll
    for (int q = 0; q < 8; q++)
        g_Rh[(size_t)(d0 + hf * 8 + q) * NV + k] = __float2half_rn(acc[q]);
}

// ---------------------------------------------------------------------------
// Fused tensor-core kernel, fp16 m16n8k16, 64-row CTAs (grid 512, occ 4),
// 32x64 warp tiles, ldmatrix A-fragments, B as [n][k] half via cp.async.
//   Stage 1: Y = x @ U  (K=1024)     Stage 2: out = x - Y @ R + b
// ---------------------------------------------------------------------------
#define XS_H 40    // xs row stride (halves); 80B, ldsm-clean (20w -> 20r%32 distinct)
#define US_H 72    // us row stride (halves); 144B = 16B-mult for cpa; 36w -> 4g+tg clean
#define YS_H 136   // ys row stride (halves); 272B; 68w -> 4r distinct

#define OFF_XS 0                     // 64*40  = 2560 halves
#define OFF_US 2560                  // 128*72 = 9216
#define OFF_YS 11776                 // 64*136 = 8704
#define SM_HALVES 20480              // 40960 bytes

__device__ __forceinline__ uint32_t smem_u32(const void* p) {
    uint32_t a;
    asm("{ .reg .u64 t; cvta.to.shared.u64 t, %1; cvt.u32.u64 %0, t; }"
        : "=r"(a) : "l"(p));
    return a;
}
__device__ __forceinline__ void cpa16(uint32_t dst, const void* src) {
    asm volatile("cp.async.cg.shared.global [%0], [%1], 16;" :: "r"(dst), "l"(src));
}
#define CPA_COMMIT() asm volatile("cp.async.commit_group;" ::: "memory")
#define CPA_WAIT()   asm volatile("cp.async.wait_group 0;" ::: "memory")

__device__ __forceinline__ void mma16(float c[4], const unsigned a[4], const unsigned b[2]) {
    asm volatile(
        "mma.sync.aligned.m16n8k16.row.col.f32.f16.f16.f32 "
        "{%0,%1,%2,%3}, {%4,%5,%6,%7}, {%8,%9}, {%0,%1,%2,%3};"
        : "+f"(c[0]), "+f"(c[1]), "+f"(c[2]), "+f"(c[3])
        : "r"(a[0]), "r"(a[1]), "r"(a[2]), "r"(a[3]), "r"(b[0]), "r"(b[1]));
}
__device__ __forceinline__ void ldsm4(unsigned a[4], uint32_t addr) {
    asm volatile("ldmatrix.sync.aligned.m8n8.x4.shared.b16 {%0,%1,%2,%3}, [%4];"
        : "=r"(a[0]), "=r"(a[1]), "=r"(a[2]), "=r"(a[3]) : "r"(addr));
}
__device__ __forceinline__ unsigned packh2(float lo, float hi) {
    __half2 h = __floats2half2_rn(lo, hi);
    return *(unsigned*)&h;
}

__global__ __launch_bounds__(128, 4) void k_fused(const float* __restrict__ x,
                                                  const float* __restrict__ bias,
                                                  float* __restrict__ out) {
    extern __shared__ __align__(16) __half smh[];
    __half* xs = smh + OFF_XS;
    __half* ys = smh + OFF_YS;
    const uint32_t sb   = smem_u32(smh);
    const uint32_t xs_b = sb + OFF_XS * 2;
    const uint32_t us_b = sb + OFF_US * 2;
    const uint32_t ys_b = sb + OFF_YS * 2;
    const unsigned* usw = (const unsigned*)(smh + OFF_US);   // word view of us

    const int tid  = threadIdx.x;
    const int lane = tid & 31, wid = tid >> 5;       // 4 warps
    const int wm = wid >> 1, wn = wid & 1;           // 2x2 warp grid
    const int grp = lane >> 2, tg = lane & 3;
    const int rowBase = blockIdx.x * 64;
    const int wrow = wm * 32;
    const int wcol = wn * 64;

    const int lmRow   = lane & 15;
    const int lmCol16 = (lane >> 4) << 4;            // byte offset: 0 or 16

    const int xr0 = tid >> 3, xc4 = tid & 7;         // x fill map (rows +16 per it)

    float acc[2][8][4];
#pragma unroll
    for (int mf = 0; mf < 2; mf++)
#pragma unroll
        for (int nf = 0; nf < 8; nf++)
#pragma unroll
            for (int q = 0; q < 4; q++) acc[mf][nf][q] = 0.f;

    // ======== Stage 1: Y = x @ U ========
    float4 p[4];
#pragma unroll
    for (int it = 0; it < 4; it++)
        p[it] = *(const float4*)&x[(size_t)(rowBase + xr0 + it * 16) * D + xc4 * 4];

    for (int kt = 0; kt < D / 32; kt++) {
        // B tile: row n = tid (128 rows x 32 halves), 4 cpa16 each
        {
            const char* src = (const char*)g_Uh + ((size_t)tid * D + kt * 32) * 2;
            const uint32_t dst = us_b + tid * (US_H * 2);
#pragma unroll
            for (int q = 0; q < 4; q++)
                cpa16(dst + q * 16, src + q * 16);
        }
        // x tile from prefetch regs -> half
#pragma unroll
        for (int it = 0; it < 4; it++) {
            uint2 hv;
            hv.x = packh2(p[it].x, p[it].y);
            hv.y = packh2(p[it].z, p[it].w);
            *(uint2*)&xs[(xr0 + it * 16) * XS_H + xc4 * 4] = hv;
        }
        CPA_COMMIT();
        CPA_WAIT();
        __syncthreads();
        if (kt + 1 < D / 32) {
#pragma unroll
            for (int it = 0; it < 4; it++)
                p[it] = *(const float4*)&x[(size_t)(rowBase + xr0 + it * 16) * D +
                                           (kt + 1) * 32 + xc4 * 4];
        }
#pragma unroll
        for (int k16 = 0; k16 < 2; k16++) {
            const int kb = k16 * 16;
            unsigned A[2][4], B[8][2];
#pragma unroll
            for (int mf = 0; mf < 2; mf++)
                ldsm4(A[mf], xs_b + (wrow + mf * 16 + lmRow) * (XS_H * 2) + kb * 2 + lmCol16);
#pragma unroll
            for (int nf = 0; nf < 8; nf++) {
                int n = wcol + nf * 8 + grp;
                B[nf][0] = usw[n * (US_H / 2) + (kb >> 1) + tg];
                B[nf][1] = usw[n * (US_H / 2) + (kb >> 1) + tg + 4];
            }
#pragma unroll
            for (int mf = 0; mf < 2; mf++)
#pragma unroll
                for (int nf = 0; nf < 8; nf++)
                    mma16(acc[mf][nf], A[mf], B[nf]);
        }
        __syncthreads();
    }

    // Y -> ys (half)
#pragma unroll
    for (int mf = 0; mf < 2; mf++)
#pragma unroll
        for (int nf = 0; nf < 8; nf++) {
            int r = wrow + mf * 16 + grp, c = wcol + nf * 8 + tg * 2;
            *(unsigned*)&ys[r * YS_H + c]       = packh2(acc[mf][nf][0], acc[mf][nf][1]);
            *(unsigned*)&ys[(r + 8) * YS_H + c] = packh2(acc[mf][nf][2], acc[mf][nf][3]);
        }

    // ======== Stage 2: out = x - Y @ R + b ========
#pragma unroll
    for (int mf = 0; mf < 2; mf++)
#pragma unroll
        for (int nf = 0; nf < 8; nf++)
#pragma unroll
            for (int q = 0; q < 4; q++) acc[mf][nf][q] = 0.f;

    for (int t = 0; t < 32; t++) {
        const int mt = t & 3, dB = (t >> 2) * 128;
        // B tile: row n = tid -> R^T[dB+n][mt*32 .. +32)
        {
            const char* src = (const char*)g_Rh + ((size_t)(dB + tid) * NV + mt * 32) * 2;
            const uint32_t dst = us_b + tid * (US_H * 2);
#pragma unroll
            for (int q = 0; q < 4; q++)
                cpa16(dst + q * 16, src + q * 16);
        }
        CPA_COMMIT();
        CPA_WAIT();
        __syncthreads();   // also covers Y->ys visibility at t=0

        const int kg0 = mt * 32;
#pragma unroll
        for (int k16 = 0; k16 < 2; k16++) {
            const int kb = k16 * 16;
            unsigned A[2][4], B[8][2];
#pragma unroll
            for (int mf = 0; mf < 2; mf++)
                ldsm4(A[mf], ys_b + (wrow + mf * 16 + lmRow) * (YS_H * 2) +
                             (kg0 + kb) * 2 + lmCol16);
#pragma unroll
            for (int nf = 0; nf < 8; nf++) {
                int n = wcol + nf * 8 + grp;
                B[nf][0] = usw[n * (US_H / 2) + (kb >> 1) + tg];
                B[nf][1] = usw[n * (US_H / 2) + (kb >> 1) + tg + 4];
            }
#pragma unroll
            for (int mf = 0; mf < 2; mf++)
#pragma unroll
                for (int nf = 0; nf < 8; nf++)
                    mma16(acc[mf][nf], A[mf], B[nf]);
        }

        if (mt == 3) {
            // epilogue: out = x + b - acc; reset acc
#pragma unroll
            for (int mf = 0; mf < 2; mf++)
#pragma unroll
                for (int nf = 0; nf < 8; nf++) {
                    int r = rowBase + wrow + mf * 16 + grp;
                    int c = dB + wcol + nf * 8 + tg * 2;
                    float2 bv = *(const float2*)&bias[c];
                    float2 x0 = *(const float2*)&x[(size_t)r * D + c];
                    float2 x1 = *(const float2*)&x[(size_t)(r + 8) * D + c];
                    float2 o0, o1;
                    o0.x = x0.x + bv.x - acc[mf][nf][0];
                    o0.y = x0.y + bv.y - acc[mf][nf][1];
                    o1.x = x1.x + bv.x - acc[mf][nf][2];
                    o1.y = x1.y + bv.y - acc[mf][nf][3];
                    *(float2*)&out[(size_t)r * D + c]       = o0;
                    *(float2*)&out[(size_t)(r + 8) * D + c] = o1;
                    acc[mf][nf][0] = 0.f; acc[mf][nf][1] = 0.f;
                    acc[mf][nf][2] = 0.f; acc[mf][nf][3] = 0.f;
                }
        }
        __syncthreads();
    }
}

// ---------------------------------------------------------------------------
extern "C" void kernel_launch(void* const* d_in, const int* in_sizes, int n_in,
                              void* d_out, int out_size) {
    const float* x = nullptr;
    const float* v = nullptr;
    const float* b = nullptr;
    for (int i = 0; i < n_in; i++) {
        if      (in_sizes[i] == BATCH * D) x = (const float*)d_in[i];
        else if (in_sizes[i] == D * NV)    v = (const float*)d_in[i];
        else if (in_sizes[i] == D)         b = (const float*)d_in[i];
    }
    float* out = (float*)d_out;

    const size_t smemM     = (2 * 128 * 129 + 64 * 65) * sizeof(float); // ~145 KB
    const size_t smemR     = (128 * 129 + 16 * 132) * sizeof(float);    // ~74 KB
    const size_t smemFused = SM_HALVES * sizeof(__half);                // 40 KB
    cudaFuncSetAttribute(k_buildM, cudaFuncAttributeMaxDynamicSharedMemorySize, (int)smemM);
    cudaFuncSetAttribute(k_mkR,    cudaFuncAttributeMaxDynamicSharedMemorySize, (int)smemR);
    cudaFuncSetAttribute(k_fused,  cudaFuncAttributeMaxDynamicSharedMemorySize, (int)smemFused);

    k_colsq <<<128, 128>>>(v);
    k_prep  <<<dim3(8, 4), dim3(32, 8)>>>(v);
    k_gram  <<<dim3(16, 8), 128>>>();
    k_buildM<<<1, 256, smemM>>>();
    k_mkR   <<<64, 256, smemR>>>();
    k_fused <<<BATCH / 64, 128, smemFused>>>(x, b, out);
}